// round 13
// baseline (speedup 1.0000x reference)
#include <cuda_runtime.h>
#include <cstdint>

#define BB 2048
#define TT 512
#define KK 32
#define FULL 0xffffffffu

#define WPB 4
#define THREADS (WPB * 32)

// per-warp: 5 bitplanes x 511 u32 = 10220 B, pad 4 -> bc buffers at 16B alignment
#define PLANE_WORDS 511
#define WARP_BYTES (5 * PLANE_WORDS * 4 + 4 + 256)   /* 10480 */
#define EC_OFF (WPB * WARP_BYTES)                    /* 41920 */
#define SMEM_TOTAL (EC_OFF + 4096)                   /* 46016 */

__device__ int d_order[BB];

// ---- counting sort by descending length (LPT schedule) ----
__global__ void order_kernel(const int* __restrict__ lens)
{
    __shared__ int hist[512];
    __shared__ int scan[512];
    const int tid = threadIdx.x;           // 512 threads
    hist[tid] = 0;
    __syncthreads();
    for (int i = tid; i < BB; i += 512)
        atomicAdd(&hist[512 - lens[i]], 1);   // len in [1,512] -> bucket [0,511]
    __syncthreads();
    scan[tid] = hist[tid];
    __syncthreads();
    for (int off = 1; off < 512; off <<= 1) {
        int add = (tid >= off) ? scan[tid - off] : 0;
        __syncthreads();
        scan[tid] += add;
        __syncthreads();
    }
    int excl = (tid == 0) ? 0 : scan[tid - 1];
    __syncthreads();
    hist[tid] = excl;                       // reuse as running offsets
    __syncthreads();
    for (int i = tid; i < BB; i += 512) {
        int pos = atomicAdd(&hist[512 - lens[i]], 1);
        d_order[pos] = i;
    }
}

__device__ __forceinline__ unsigned long long pack2(float lo, float hi) {
    unsigned long long d;
    asm("mov.b64 %0, {%1,%2};" : "=l"(d) : "f"(lo), "f"(hi));
    return d;
}
__device__ __forceinline__ void unpack2(unsigned long long d, float& lo, float& hi) {
    asm("mov.b64 {%0,%1}, %2;" : "=f"(lo), "=f"(hi) : "l"(d));
}
__device__ __forceinline__ unsigned long long fma2(unsigned long long a,
                                                   unsigned long long b,
                                                   unsigned long long c) {
    unsigned long long d;
    asm("fma.rn.f32x2 %0, %1, %2, %3;" : "=l"(d) : "l"(a), "l"(b), "l"(c));
    return d;
}
__device__ __forceinline__ unsigned long long add2(unsigned long long a,
                                                   unsigned long long b) {
    unsigned long long d;
    asm("add.rn.f32x2 %0, %1, %2;" : "=l"(d) : "l"(a), "l"(b));
    return d;
}

__global__ void __launch_bounds__(THREADS, 5)
crf_kernel(const float* __restrict__ pot,      // [B,T,K]
           const float* __restrict__ trans,    // [K,K]
           const int*   __restrict__ lens,     // [B]
           const int*   __restrict__ tags,     // [B,T]
           float*       __restrict__ out)      // [B*T + B + B] floats
{
    extern __shared__ unsigned char smem[];
    const int lane = threadIdx.x & 31;
    const int w    = threadIdx.x >> 5;

    uint32_t* planes = (uint32_t*)(smem + (size_t)w * WARP_BYTES);  // [5][511]
    float* bcV = (float*)(smem + (size_t)w * WARP_BYTES + (5 * PLANE_WORDS * 4 + 4));
    float* bcE = bcV + 32;
    ulonglong2* EcS = (ulonglong2*)(smem + EC_OFF);  // [8][32] (2 packed pairs each)

    const int b = d_order[blockIdx.x * WPB + w];

    // column k=lane of transitions in regs
    float Tc[KK];
#pragma unroll
    for (int j = 0; j < KK; j++) Tc[j] = trans[j * KK + lane];

    // exp(column) packed pairs -> block-shared table (lane-dependent only)
    if (w == 0) {
#pragma unroll
        for (int qq = 0; qq < 8; qq++) {
            ulonglong2 u;
            u.x = pack2(__expf(Tc[4 * qq + 0]), __expf(Tc[4 * qq + 1]));
            u.y = pack2(__expf(Tc[4 * qq + 2]), __expf(Tc[4 * qq + 3]));
            EcS[qq * 32 + lane] = u;
        }
    }
    __syncthreads();

    const int len = lens[b];
    const float* pb = pot + (size_t)b * TT * KK;

    float av = pb[lane];       // viterbi alpha
    float al = av;             // logsumexp alpha

    // depth-4 potential prefetch pipeline (hides DRAM latency)
    float p1 = pb[1 * KK + lane];
    float p2 = pb[2 * KK + lane];
    float p3 = pb[3 * KK + lane];
    float p4 = pb[4 * KK + lane];

    for (int t = 1; t < len; ++t) {
        const float pc = p1;
        p1 = p2; p2 = p3; p3 = p4;
        const int tn = (t + 4 < TT) ? (t + 4) : (TT - 1);
        p4 = pb[tn * KK + lane];

        // lane-0 stabilizer: cross-lane alpha spread is bounded, exp stays finite
        const float m = __shfl_sync(FULL, al, 0);
        const float e = __expf(al - m);

        __syncwarp();              // prior iteration's reads of bcV/bcE done
        bcV[lane] = av;
        bcE[lane] = e;
        __syncwarp();

        // ---- viterbi scores with fused tournament level 1 (exact first-index ties)
        float vm[16]; int tim[16];
        {
            const float4* b4 = (const float4*)bcV;
#pragma unroll
            for (int q = 0; q < 8; q++) {
                float4 x = b4[q];
                float a0 = x.x + Tc[4*q+0];
                float a1 = x.y + Tc[4*q+1];
                float a2 = x.z + Tc[4*q+2];
                float a3 = x.w + Tc[4*q+3];
                bool u0 = a0 >= a1;          // keep-left on tie -> first index
                bool u1 = a2 >= a3;
                vm[2*q]   = u0 ? a0 : a1;  tim[2*q]   = u0 ? (4*q)   : (4*q+1);
                vm[2*q+1] = u1 ? a2 : a3;  tim[2*q+1] = u1 ? (4*q+2) : (4*q+3);
            }
        }
#pragma unroll
        for (int wd = 1; wd < 16; wd <<= 1) {
#pragma unroll
            for (int i = 0; i < 16; i += 2 * wd) {
                bool p = vm[i] >= vm[i + wd];
                vm[i]  = p ? vm[i]  : vm[i + wd];
                tim[i] = p ? tim[i] : tim[i + wd];
            }
        }
        av = pc + vm[0];

        // ---- bitplane backpointer store: 5 ballots, lanes 0-4 store one word each
        {
            const int bpv = tim[0];
            unsigned m0 = __ballot_sync(FULL, bpv & 1);
            unsigned m1 = __ballot_sync(FULL, bpv & 2);
            unsigned m2 = __ballot_sync(FULL, bpv & 4);
            unsigned m3 = __ballot_sync(FULL, bpv & 8);
            unsigned m4 = __ballot_sync(FULL, bpv & 16);
            unsigned mv = (lane == 1) ? m1 : (lane == 2) ? m2
                        : (lane == 3) ? m3 : (lane == 4) ? m4 : m0;
            if (lane < 5) planes[lane * PLANE_WORDS + (t - 1)] = mv;
        }

        // ---- logsumexp: packed f32x2 inner product with exp(transitions) ----
        unsigned long long s0 = 0ull, s1 = 0ull, s2 = 0ull, s3 = 0ull;
        {
            const ulonglong2* e2 = (const ulonglong2*)bcE;
#pragma unroll
            for (int q = 0; q < 8; q += 2) {
                ulonglong2 ya = e2[q];
                ulonglong2 yb = e2[q + 1];
                ulonglong2 Ea = EcS[q * 32 + lane];
                ulonglong2 Eb = EcS[(q + 1) * 32 + lane];
                s0 = fma2(ya.x, Ea.x, s0);
                s1 = fma2(ya.y, Ea.y, s1);
                s2 = fma2(yb.x, Eb.x, s2);
                s3 = fma2(yb.y, Eb.y, s3);
            }
        }
        s0 = add2(s0, s1);
        s2 = add2(s2, s3);
        s0 = add2(s0, s2);
        float sa, sb;
        unpack2(s0, sa, sb);
        al = pc + m + __logf(sa + sb);
    }

    // ---- best score + last tag (first-index argmax over lanes) ----
    float bv = av; int bi = lane;
#pragma unroll
    for (int d = 16; d; d >>= 1) {
        float ov = __shfl_xor_sync(FULL, bv, d);
        int   oi = __shfl_xor_sync(FULL, bi, d);
        if (ov > bv || (ov == bv && oi < bi)) { bv = ov; bi = oi; }
    }

    // ---- log partition ----
    float m = al;
#pragma unroll
    for (int d = 16; d; d >>= 1)
        m = fmaxf(m, __shfl_xor_sync(FULL, m, d));
    float s = __expf(al - m);
#pragma unroll
    for (int d = 16; d; d >>= 1)
        s += __shfl_xor_sync(FULL, s, d);
    const float logZ = m + __logf(s);

    // ---- sequence score of given tags (masked) ----
    const int* tgb = tags + (size_t)b * TT;
    float sc = 0.f;
#pragma unroll
    for (int i = 0; i < TT / 32; i++) {
        int t = lane + 32 * i;
        if (t < len) {
            int tg = tgb[t];
            sc += pb[t * KK + tg];
            if (t < len - 1) {
                int tg1 = tgb[t + 1];
                sc += trans[tg * KK + tg1];
            }
        }
    }
#pragma unroll
    for (int d = 16; d; d >>= 1)
        sc += __shfl_xor_sync(FULL, sc, d);

    // ---- outputs ----
    float* outTags = out + (size_t)b * TT;
    const float ltf = (float)bi;
    for (int i = len - 1 + lane; i < TT; i += 32) outTags[i] = ltf;

    if (lane == 0) {
        int carry = bi;
        for (int t = len - 1; t >= 1; --t) {
            const int tt = t - 1;
            unsigned w0 = planes[tt];
            unsigned w1 = planes[PLANE_WORDS + tt];
            unsigned w2 = planes[2 * PLANE_WORDS + tt];
            unsigned w3 = planes[3 * PLANE_WORDS + tt];
            unsigned w4 = planes[4 * PLANE_WORDS + tt];
            carry =  ((w0 >> carry) & 1)
                  | (((w1 >> carry) & 1) << 1)
                  | (((w2 >> carry) & 1) << 2)
                  | (((w3 >> carry) & 1) << 3)
                  | (((w4 >> carry) & 1) << 4);
            outTags[tt] = (float)carry;
        }
        out[(size_t)BB * TT + b]      = bv;         // best_score
        out[(size_t)BB * TT + BB + b] = sc - logZ;  // log_likelihood
    }
}

extern "C" void kernel_launch(void* const* d_in, const int* in_sizes, int n_in,
                              void* d_out, int out_size)
{
    const float* pot   = (const float*)d_in[0];
    const float* trans = (const float*)d_in[1];
    const int*   lens  = (const int*)d_in[2];
    const int*   tags  = (const int*)d_in[3];
    float* out = (float*)d_out;

    static bool attr_set = false;
    if (!attr_set) {
        cudaFuncSetAttribute(crf_kernel, cudaFuncAttributeMaxDynamicSharedMemorySize,
                             SMEM_TOTAL);
        attr_set = true;
    }

    order_kernel<<<1, 512>>>(lens);
    crf_kernel<<<BB / WPB, THREADS, SMEM_TOTAL>>>(pot, trans, lens, tags, out);
}